// round 4
// baseline (speedup 1.0000x reference)
#include <cuda_runtime.h>
#include <math.h>
#include <stdint.h>

// ---------------- problem constants ----------------
#define Bq   64
#define Tq   512
#define Hq   1024
#define G4   4096          // 4*H
#define MTOT (Bq * Tq)     // 32768 rows for time-parallel GEMMs
#define NCTA 128           // persistent recurrence grid (<=148 SMs -> co-resident)

// recurrence smem: Hs[64][132] + Ws[128][40]
#define HS_STRIDE 132
#define WS_STRIDE 40
#define LSTM_SMEM ((64 * HS_STRIDE + 128 * WS_STRIDE) * 4)

// ---------------- scratch (device globals; no allocations allowed) ----------
__device__ float g_enc_xproj[(size_t)MTOT * G4];   // [B*T, 4H], row = b*T + t
__device__ float g_dec_xproj[(size_t)MTOT * G4];
__device__ float g_dec_hs  [(size_t)MTOT * Hq];    // decoder hidden states
__device__ float g_h       [2 * Bq * Hq];          // ping-pong h
__device__ float g_c       [Bq * Hq];
__device__ float g_mlp1    [(size_t)MTOT * 256];
__device__ float g_mlp2    [(size_t)MTOT * 128];
__device__ float g_Wt_enc  [(size_t)G4 * Hq];      // tf32-rounded, blocked [cta][k][32]
__device__ float g_Wt_dec  [(size_t)G4 * Hq];
__device__ unsigned g_bar;                          // grid barrier counter

// ---------------- small helpers --------------------------------------------
__device__ __forceinline__ float tf32r(float x) {
    uint32_t u;
    asm("cvt.rna.tf32.f32 %0, %1;" : "=r"(u) : "f"(x));
    return __uint_as_float(u);
}

__device__ __forceinline__ void mma_tf32(float c[4],
                                         uint32_t a0, uint32_t a1, uint32_t a2, uint32_t a3,
                                         uint32_t b0, uint32_t b1) {
    asm volatile(
        "mma.sync.aligned.m16n8k8.row.col.f32.tf32.tf32.f32 "
        "{%0,%1,%2,%3}, {%4,%5,%6,%7}, {%8,%9}, {%0,%1,%2,%3};"
        : "+f"(c[0]), "+f"(c[1]), "+f"(c[2]), "+f"(c[3])
        : "r"(a0), "r"(a1), "r"(a2), "r"(a3), "r"(b0), "r"(b1));
}

// ---------------- zero-init h0, c0, barrier (re-zero every replay) ---------
__global__ void zero_hc_kernel() {
    int i = blockIdx.x * blockDim.x + threadIdx.x;
    if (i < Bq * Hq) { g_h[i] = 0.f; g_c[i] = 0.f; }
    if (i == 0) g_bar = 0u;
}

// ---------------- Whh prep: tf32 round + blocked relayout -------------------
// Wt[((cta*1024)+k)*32 + cc] = tf32(Whh[(g*1024 + cta*8 + jj)*1024 + k]),
// where g = cc>>3, jj = cc&7. One thread per (cta, cc, k-quad).
__global__ __launch_bounds__(256)
void prep_w_kernel(const float* __restrict__ Whh, float* __restrict__ Wt) {
    int idx = blockIdx.x * 256 + threadIdx.x;   // 0 .. 128*32*256-1
    int k4  = idx & 255;
    int cc  = (idx >> 8) & 31;
    int cta = idx >> 13;
    int g = cc >> 3, jj = cc & 7;
    const float4 v = *(const float4*)&Whh[(size_t)(g * Hq + cta * 8 + jj) * Hq + k4 * 4];
    size_t base = ((size_t)cta * Hq + k4 * 4) * 32 + cc;
    Wt[base + 0 * 32] = tf32r(v.x);
    Wt[base + 1 * 32] = tf32r(v.y);
    Wt[base + 2 * 32] = tf32r(v.z);
    Wt[base + 3 * 32] = tf32r(v.w);
}

// ---------------- generic fp32 GEMM: C[M,N] = A[M,K] @ W[N,K]^T + b1 + b2 ---
#define GBM 128
#define GBN 64
#define GBK 32

__global__ __launch_bounds__(256)
void gemm_bias_kernel(const float* __restrict__ A, const float* __restrict__ W,
                      const float* __restrict__ bias1, const float* __restrict__ bias2,
                      float* __restrict__ C, int M, int N, int K, int relu)
{
    __shared__ alignas(16) float As[GBK][GBM + 4];
    __shared__ alignas(16) float Ws[GBK][GBN + 4];

    const int bm = blockIdx.y * GBM;
    const int bn = blockIdx.x * GBN;
    const int tid = threadIdx.x;
    const int ct = tid & 15;
    const int rt = tid >> 4;

    float acc[8][4];
#pragma unroll
    for (int i = 0; i < 8; i++)
#pragma unroll
        for (int j = 0; j < 4; j++) acc[i][j] = 0.f;

    const int kq = tid & 7;
    const int lr = tid >> 3;

    for (int k0 = 0; k0 < K; k0 += GBK) {
#pragma unroll
        for (int p = 0; p < 4; p++) {
            int m = lr + p * 32;
            float4 v = *(const float4*)&A[(size_t)(bm + m) * K + k0 + kq * 4];
            As[kq * 4 + 0][m] = v.x; As[kq * 4 + 1][m] = v.y;
            As[kq * 4 + 2][m] = v.z; As[kq * 4 + 3][m] = v.w;
        }
#pragma unroll
        for (int p = 0; p < 2; p++) {
            int n = lr + p * 32;
            float4 v = *(const float4*)&W[(size_t)(bn + n) * K + k0 + kq * 4];
            Ws[kq * 4 + 0][n] = v.x; Ws[kq * 4 + 1][n] = v.y;
            Ws[kq * 4 + 2][n] = v.z; Ws[kq * 4 + 3][n] = v.w;
        }
        __syncthreads();

#pragma unroll
        for (int kk = 0; kk < GBK; kk++) {
            float4 a0 = *(const float4*)&As[kk][rt * 8];
            float4 a1 = *(const float4*)&As[kk][rt * 8 + 4];
            float4 b  = *(const float4*)&Ws[kk][ct * 4];
            float av[8] = {a0.x, a0.y, a0.z, a0.w, a1.x, a1.y, a1.z, a1.w};
            float bv[4] = {b.x, b.y, b.z, b.w};
#pragma unroll
            for (int i = 0; i < 8; i++)
#pragma unroll
                for (int j = 0; j < 4; j++) acc[i][j] += av[i] * bv[j];
        }
        __syncthreads();
    }

#pragma unroll
    for (int i = 0; i < 8; i++) {
        size_t m = (size_t)(bm + rt * 8 + i);
#pragma unroll
        for (int j = 0; j < 4; j++) {
            int n = bn + ct * 4 + j;
            float v = acc[i][j];
            if (bias1) v += bias1[n];
            if (bias2) v += bias2[n];
            if (relu)  v = fmaxf(v, 0.f);
            C[m * N + n] = v;
        }
    }
}

// ---------------- persistent LSTM recurrence (tf32 tensor-core) -------------
__device__ __forceinline__ void grid_bar(unsigned target) {
    __syncthreads();
    if (threadIdx.x == 0) {
        __threadfence();
        atomicAdd(&g_bar, 1u);
        while (atomicAdd(&g_bar, 0u) < target) __nanosleep(64);
        __threadfence();
    }
    __syncthreads();
}

__global__ __launch_bounds__(256, 1)
void lstm_persistent_kernel(const float* __restrict__ enc_xp,
                            const float* __restrict__ dec_xp,
                            float* __restrict__ dec_hs)
{
    extern __shared__ float smem[];
    float* Hs = smem;                  // [64][HS_STRIDE], h tile (tf32-rounded)
    float* Ws = smem + 64 * HS_STRIDE; // [128][WS_STRIDE], W tile

    const int tid  = threadIdx.x;
    const int wid  = tid >> 5;
    const int lane = tid & 31;
    const int g    = lane >> 2;   // groupID 0..7
    const int tq   = lane & 3;    // threadID_in_group 0..3
    const int wm   = wid >> 1;    // warp m-group 0..3 (rows wm*16..+15)
    const int wn   = wid & 1;     // warp n-group 0..1 (cols wn*16..+15)
    const int r0   = wm * 16 + g;
    const int cb   = wn * 16;
    const int j0   = blockIdx.x * 8;

    const float* WtE = g_Wt_enc + (size_t)blockIdx.x * Hq * 32;
    const float* WtD = g_Wt_dec + (size_t)blockIdx.x * Hq * 32;

    for (int s = 0; s < 2 * Tq; s++) {
        const int enc = (s < Tq);
        const int t   = enc ? s : (s - Tq);
        const float* __restrict__ xproj = enc ? enc_xp : dec_xp;
        const float* __restrict__ Wt    = enc ? WtE : WtD;
        const float* __restrict__ h_in  = g_h + (s & 1) * Bq * Hq;
        float* __restrict__ h_out       = g_h + ((s + 1) & 1) * Bq * Hq;

        float acc[2][4] = {{0.f,0.f,0.f,0.f},{0.f,0.f,0.f,0.f}};

        for (int kt = 0; kt < 8; kt++) {
            const int k0 = kt * 128;
            // stage h tile [64][128] (tf32-rounded)
#pragma unroll
            for (int p = 0; p < 8; p++) {
                int q = p * 256 + tid;
                int row = q >> 5, c4 = (q & 31) * 4;
                float4 v = *(const float4*)&h_in[row * Hq + k0 + c4];
                float4 r;
                r.x = tf32r(v.x); r.y = tf32r(v.y); r.z = tf32r(v.z); r.w = tf32r(v.w);
                *(float4*)&Hs[row * HS_STRIDE + c4] = r;
            }
            // stage W tile [128][32] (already tf32)
            {
                const float4* wsrc = (const float4*)(Wt + (size_t)k0 * 32);
#pragma unroll
                for (int p = 0; p < 4; p++) {
                    int q = p * 256 + tid;
                    int k = q >> 3, c4 = (q & 7) * 4;
                    float4 v = wsrc[q];
                    *(float4*)&Ws[k * WS_STRIDE + c4] = v;
                }
            }
            __syncthreads();

#pragma unroll
            for (int ks = 0; ks < 16; ks++) {
                const int kb = ks * 8;
                uint32_t a0 = __float_as_uint(Hs[r0 * HS_STRIDE + kb + tq]);
                uint32_t a1 = __float_as_uint(Hs[(r0 + 8) * HS_STRIDE + kb + tq]);
                uint32_t a2 = __float_as_uint(Hs[r0 * HS_STRIDE + kb + tq + 4]);
                uint32_t a3 = __float_as_uint(Hs[(r0 + 8) * HS_STRIDE + kb + tq + 4]);
#pragma unroll
                for (int nt = 0; nt < 2; nt++) {
                    uint32_t b0 = __float_as_uint(Ws[(kb + tq) * WS_STRIDE + cb + nt * 8 + g]);
                    uint32_t b1 = __float_as_uint(Ws[(kb + tq + 4) * WS_STRIDE + cb + nt * 8 + g]);
                    mma_tf32(acc[nt], a0, a1, a2, a3, b0, b1);
                }
            }
            __syncthreads();
        }

        // write accumulators to Cs (reuse Hs memory, stride 33)
        float* Cs = Hs;
#pragma unroll
        for (int nt = 0; nt < 2; nt++) {
            int col = cb + nt * 8 + 2 * tq;
            Cs[r0 * 33 + col]           = acc[nt][0];
            Cs[r0 * 33 + col + 1]       = acc[nt][1];
            Cs[(r0 + 8) * 33 + col]     = acc[nt][2];
            Cs[(r0 + 8) * 33 + col + 1] = acc[nt][3];
        }
        __syncthreads();

        // pointwise LSTM update: 64 rows x 8 cols = 512 elements
        for (int idx = tid; idx < Bq * 8; idx += 256) {
            int m = idx >> 3, jj = idx & 7;
            size_t xrow = ((size_t)m * Tq + t) * G4;
            float ig = Cs[m * 33 + jj]      + xproj[xrow + 0 * Hq + j0 + jj];
            float fg = Cs[m * 33 + 8 + jj]  + xproj[xrow + 1 * Hq + j0 + jj];
            float gg = Cs[m * 33 + 16 + jj] + xproj[xrow + 2 * Hq + j0 + jj];
            float og = Cs[m * 33 + 24 + jj] + xproj[xrow + 3 * Hq + j0 + jj];
            float is = 1.f / (1.f + expf(-ig));
            float fs = 1.f / (1.f + expf(-fg));
            float gt = tanhf(gg);
            float os = 1.f / (1.f + expf(-og));
            int col = j0 + jj;
            float cn = fs * g_c[m * Hq + col] + is * gt;
            float hn = os * tanhf(cn);
            g_c[m * Hq + col] = cn;
            h_out[m * Hq + col] = hn;
            if (!enc) dec_hs[((size_t)m * Tq + t) * Hq + col] = hn;
        }

        grid_bar((unsigned)(s + 1) * NCTA);
    }
}

// ---------------- host driver ----------------------------------------------
extern "C" void kernel_launch(void* const* d_in, const int* in_sizes, int n_in,
                              void* d_out, int out_size)
{
    const float* input_seq  = (const float*)d_in[0];   // [64,512,256]
    const float* target_seq = (const float*)d_in[1];   // [64,512,1024]
    const float* enc_Wih = (const float*)d_in[2];
    const float* enc_Whh = (const float*)d_in[3];
    const float* enc_bih = (const float*)d_in[4];
    const float* enc_bhh = (const float*)d_in[5];
    const float* dec_Wih = (const float*)d_in[6];
    const float* dec_Whh = (const float*)d_in[7];
    const float* dec_bih = (const float*)d_in[8];
    const float* dec_bhh = (const float*)d_in[9];
    const float* W1 = (const float*)d_in[10];
    const float* b1 = (const float*)d_in[11];
    const float* W2 = (const float*)d_in[12];
    const float* b2 = (const float*)d_in[13];
    const float* W3 = (const float*)d_in[14];
    const float* b3 = (const float*)d_in[15];
    float* out = (float*)d_out;

    float *enc_xp, *dec_xp, *dec_hs, *m1, *m2, *wte, *wtd;
    cudaGetSymbolAddress((void**)&enc_xp, g_enc_xproj);
    cudaGetSymbolAddress((void**)&dec_xp, g_dec_xproj);
    cudaGetSymbolAddress((void**)&dec_hs, g_dec_hs);
    cudaGetSymbolAddress((void**)&m1,     g_mlp1);
    cudaGetSymbolAddress((void**)&m2,     g_mlp2);
    cudaGetSymbolAddress((void**)&wte,    g_Wt_enc);
    cudaGetSymbolAddress((void**)&wtd,    g_Wt_dec);

    static int smem_set = 0;
    if (!smem_set) {
        cudaFuncSetAttribute(lstm_persistent_kernel,
                             cudaFuncAttributeMaxDynamicSharedMemorySize, LSTM_SMEM);
        smem_set = 1;
    }

    // h0 = c0 = 0, barrier = 0 (must re-zero every replay)
    zero_hc_kernel<<<(Bq * Hq + 255) / 256, 256>>>();

    // Whh prep: tf32 round + blocked relayout
    prep_w_kernel<<<G4 * Hq / 4 / 256, 256>>>(enc_Whh, wte);
    prep_w_kernel<<<G4 * Hq / 4 / 256, 256>>>(dec_Whh, wtd);

    // time-parallel input projections (biases folded here)
    gemm_bias_kernel<<<dim3(G4 / GBN, MTOT / GBM), 256>>>(
        input_seq, enc_Wih, enc_bih, enc_bhh, enc_xp, MTOT, G4, 256, 0);
    gemm_bias_kernel<<<dim3(G4 / GBN, MTOT / GBM), 256>>>(
        target_seq, dec_Wih, dec_bih, dec_bhh, dec_xp, MTOT, G4, Hq, 0);

    // sequential recurrence: one persistent launch for all 1024 steps
    lstm_persistent_kernel<<<NCTA, 256, LSTM_SMEM>>>(enc_xp, dec_xp, dec_hs);

    // MLP head (vectorized over all B*T rows)
    gemm_bias_kernel<<<dim3(256 / GBN, MTOT / GBM), 256>>>(
        dec_hs, W1, b1, nullptr, m1, MTOT, 256, Hq, 1);
    gemm_bias_kernel<<<dim3(128 / GBN, MTOT / GBM), 256>>>(
        m1, W2, b2, nullptr, m2, MTOT, 128, 256, 1);
    gemm_bias_kernel<<<dim3(256 / GBN, MTOT / GBM), 256>>>(
        m2, W3, b3, nullptr, out, MTOT, 256, 128, 0);
}

// round 5
// speedup vs baseline: 1.4829x; 1.4829x over previous
#include <cuda_runtime.h>
#include <math.h>
#include <stdint.h>

#define Bq   64
#define Tq   512
#define Hq   1024
#define G4   4096
#define MTOT (Bq * Tq)
#define NCTA 128

#define HST     132
#define CHUNK_F (64 * HST)          // 8448 floats per h chunk buffer
#define WB_F    32768               // resident W: 8192 float4
#define LSTM_SMEM ((WB_F + 2 * CHUNK_F) * 4)   // 198656 B

// ---------------- device scratch ----------------
__device__ float g_enc_xproj[(size_t)MTOT * G4];
__device__ float g_dec_xproj[(size_t)MTOT * G4];
__device__ float g_dec_hs  [(size_t)MTOT * Hq];
__device__ float g_h       [2 * Bq * Hq];
__device__ float g_mlp1    [(size_t)MTOT * 256];
__device__ float g_mlp2    [(size_t)MTOT * 128];
__device__ float g_Wt_enc  [(size_t)G4 * Hq];   // fragment-packed per CTA
__device__ float g_Wt_dec  [(size_t)G4 * Hq];
__device__ unsigned g_bar;

// ---------------- helpers ----------------
__device__ __forceinline__ float tf32r(float x) {
    uint32_t u; asm("cvt.rna.tf32.f32 %0, %1;" : "=r"(u) : "f"(x));
    return __uint_as_float(u);
}
__device__ __forceinline__ uint32_t fu(float x) { return __float_as_uint(x); }
__device__ __forceinline__ void mma_tf32(float c[4],
    uint32_t a0, uint32_t a1, uint32_t a2, uint32_t a3, uint32_t b0, uint32_t b1) {
    asm volatile(
        "mma.sync.aligned.m16n8k8.row.col.f32.tf32.tf32.f32 "
        "{%0,%1,%2,%3}, {%4,%5,%6,%7}, {%8,%9}, {%0,%1,%2,%3};"
        : "+f"(c[0]), "+f"(c[1]), "+f"(c[2]), "+f"(c[3])
        : "r"(a0), "r"(a1), "r"(a2), "r"(a3), "r"(b0), "r"(b1));
}
__device__ __forceinline__ float sigm(float x) { return 1.f / (1.f + expf(-x)); }

// ---------------- init ----------------
__global__ void zero_hc_kernel() {
    int i = blockIdx.x * blockDim.x + threadIdx.x;
    if (i < Bq * Hq) g_h[i] = 0.f;
    if (i == 0) g_bar = 0u;
}

// ---------------- Whh prep: tf32 + fragment-packed layout -------------------
// dst[cta*8192 + (gks*2+wn)*32 + lane] = {W(c0,k0),W(c0,k1),W(c1,k0),W(c1,k1)}
// c0 = wn*16+g, c1 = c0+8 (CTA-local gate cols), k0 = gks*8+tq, k1 = k0+4.
__global__ __launch_bounds__(256)
void prep_w_kernel(const float* __restrict__ Whh, float4* __restrict__ Wt4) {
    int idx  = blockIdx.x * 256 + threadIdx.x;
    int lane = idx & 31;
    int wn   = (idx >> 5) & 1;
    int gks  = (idx >> 6) & 127;
    int cta  = idx >> 13;
    int g = lane >> 2, tq = lane & 3;
    int k0 = gks * 8 + tq, k1 = k0 + 4;
    int c0 = wn * 16 + g,  c1 = c0 + 8;
    size_t r0 = (size_t)((c0 >> 3) * Hq + cta * 8 + (c0 & 7)) * Hq;
    size_t r1 = (size_t)((c1 >> 3) * Hq + cta * 8 + (c1 & 7)) * Hq;
    float4 v;
    v.x = tf32r(Whh[r0 + k0]); v.y = tf32r(Whh[r0 + k1]);
    v.z = tf32r(Whh[r1 + k0]); v.w = tf32r(Whh[r1 + k1]);
    Wt4[idx] = v;
}

// ---------------- tf32 GEMM: C[M,N] = A[M,K] @ W[N,K]^T (+bias, relu) -------
// BM=128 BN=128 BK=32, 8 warps (4m x 2n), warp tile m32 n64.
__global__ __launch_bounds__(256)
void gemm_tf32_kernel(const float* __restrict__ A, const float* __restrict__ W,
                      const float* __restrict__ bias1, const float* __restrict__ bias2,
                      float* __restrict__ C, int M, int N, int K, int relu)
{
    __shared__ float As[32][132];
    __shared__ float Bs[32][132];
    const int tid = threadIdx.x;
    const int lane = tid & 31, wid = tid >> 5;
    const int g = lane >> 2, tq = lane & 3;
    const int wm = wid >> 1, wn = wid & 1;
    const int bm = blockIdx.y * 128, bn = blockIdx.x * 128;
    const int kq = tid & 7, lr = tid >> 3;

    float acc[2][8][4] = {};
    float4 pa[4], pb[4];

#pragma unroll
    for (int p = 0; p < 4; p++) {
        pa[p] = *(const float4*)&A[(size_t)(bm + lr + p * 32) * K + kq * 4];
        pb[p] = *(const float4*)&W[(size_t)(bn + lr + p * 32) * K + kq * 4];
    }
#pragma unroll
    for (int p = 0; p < 4; p++) {
        int m = lr + p * 32;
        As[kq*4+0][m] = tf32r(pa[p].x); As[kq*4+1][m] = tf32r(pa[p].y);
        As[kq*4+2][m] = tf32r(pa[p].z); As[kq*4+3][m] = tf32r(pa[p].w);
        Bs[kq*4+0][m] = tf32r(pb[p].x); Bs[kq*4+1][m] = tf32r(pb[p].y);
        Bs[kq*4+2][m] = tf32r(pb[p].z); Bs[kq*4+3][m] = tf32r(pb[p].w);
    }
    __syncthreads();

    const int NK = K / 32;
    for (int kt = 0; kt < NK; kt++) {
        if (kt + 1 < NK) {
            int k0 = (kt + 1) * 32;
#pragma unroll
            for (int p = 0; p < 4; p++) {
                pa[p] = *(const float4*)&A[(size_t)(bm + lr + p * 32) * K + k0 + kq * 4];
                pb[p] = *(const float4*)&W[(size_t)(bn + lr + p * 32) * K + k0 + kq * 4];
            }
        }
#pragma unroll
        for (int ks = 0; ks < 4; ks++) {
            const int kb = ks * 8;
            uint32_t a[2][4], b[8][2];
#pragma unroll
            for (int mf = 0; mf < 2; mf++) {
                int r = wm * 32 + mf * 16 + g;
                a[mf][0] = fu(As[kb + tq][r]);     a[mf][1] = fu(As[kb + tq][r + 8]);
                a[mf][2] = fu(As[kb + tq + 4][r]); a[mf][3] = fu(As[kb + tq + 4][r + 8]);
            }
#pragma unroll
            for (int nf = 0; nf < 8; nf++) {
                int cn = wn * 64 + nf * 8 + g;
                b[nf][0] = fu(Bs[kb + tq][cn]);
                b[nf][1] = fu(Bs[kb + tq + 4][cn]);
            }
#pragma unroll
            for (int mf = 0; mf < 2; mf++)
#pragma unroll
                for (int nf = 0; nf < 8; nf++)
                    mma_tf32(acc[mf][nf], a[mf][0], a[mf][1], a[mf][2], a[mf][3],
                             b[nf][0], b[nf][1]);
        }
        __syncthreads();
        if (kt + 1 < NK) {
#pragma unroll
            for (int p = 0; p < 4; p++) {
                int m = lr + p * 32;
                As[kq*4+0][m] = tf32r(pa[p].x); As[kq*4+1][m] = tf32r(pa[p].y);
                As[kq*4+2][m] = tf32r(pa[p].z); As[kq*4+3][m] = tf32r(pa[p].w);
                Bs[kq*4+0][m] = tf32r(pb[p].x); Bs[kq*4+1][m] = tf32r(pb[p].y);
                Bs[kq*4+2][m] = tf32r(pb[p].z); Bs[kq*4+3][m] = tf32r(pb[p].w);
            }
            __syncthreads();
        }
    }

#pragma unroll
    for (int mf = 0; mf < 2; mf++) {
        int row = bm + wm * 32 + mf * 16 + g;
#pragma unroll
        for (int nf = 0; nf < 8; nf++) {
            int col = bn + wn * 64 + nf * 8 + 2 * tq;
            float b0 = 0.f, b1 = 0.f;
            if (bias1) { b0 = bias1[col]; b1 = bias1[col + 1]; }
            if (bias2) { b0 += bias2[col]; b1 += bias2[col + 1]; }
            float v0 = acc[mf][nf][0] + b0, v1 = acc[mf][nf][1] + b1;
            float v2 = acc[mf][nf][2] + b0, v3 = acc[mf][nf][3] + b1;
            if (relu) { v0 = fmaxf(v0, 0.f); v1 = fmaxf(v1, 0.f);
                        v2 = fmaxf(v2, 0.f); v3 = fmaxf(v3, 0.f); }
            float2 lo = {v0, v1}, hi = {v2, v3};
            *(float2*)&C[(size_t)row * N + col] = lo;
            *(float2*)&C[(size_t)(row + 8) * N + col] = hi;
        }
    }
}

// ---------------- grid barrier (arrive-once + volatile poll) ----------------
__device__ __forceinline__ void grid_bar(unsigned target) {
    __syncthreads();
    if (threadIdx.x == 0) {
        __threadfence();
        atomicAdd(&g_bar, 1u);
        volatile unsigned* p = &g_bar;
        while (*p < target) { }
        __threadfence();
    }
    __syncthreads();
}

// ---------------- persistent LSTM recurrence --------------------------------
__global__ __launch_bounds__(256, 1)
void lstm_persistent_kernel(const float* __restrict__ enc_xp,
                            const float* __restrict__ dec_xp,
                            float* __restrict__ dec_hs)
{
    extern __shared__ float smem[];
    float4* Wb4 = (float4*)smem;            // resident W (128 KB)
    float*  HsA = smem + WB_F;              // 2 chunk buffers

    const int tid  = threadIdx.x;
    const int lane = tid & 31, wid = tid >> 5;
    const int g = lane >> 2, tq = lane & 3;
    const int wm = wid >> 1, wn = wid & 1;  // 4m x 2n warps
    const int r0 = wm * 16 + g;
    const int j0 = blockIdx.x * 8;
    const int ldrow = tid >> 5;             // stager: base row 0..7
    const int ldc4  = (tid & 31) * 4;       // stager: 4-col group
    const int pm = tid >> 2;                // pointwise row 0..63
    const int pj = (tid & 3) * 2;           // pointwise col pair
    const int pcol = j0 + pj;

    const float4* WtE = (const float4*)g_Wt_enc + (size_t)blockIdx.x * 8192;
    const float4* WtD = (const float4*)g_Wt_dec + (size_t)blockIdx.x * 8192;

    float2 creg = {0.f, 0.f};               // cell state lives in registers

    for (int s = 0; s < 2 * Tq; s++) {
        const int enc = (s < Tq);
        const int t   = enc ? s : (s - Tq);
        const float* __restrict__ xproj = enc ? enc_xp : dec_xp;
        const float* __restrict__ h_in  = g_h + (s & 1) * (Bq * Hq);
        float* __restrict__ h_out       = g_h + ((s + 1) & 1) * (Bq * Hq);

        if (s == 0 || s == Tq) {            // load resident W once per phase
            const float4* src = enc ? WtE : WtD;
#pragma unroll
            for (int j = 0; j < 32; j++) Wb4[j * 256 + tid] = src[j * 256 + tid];
            __syncthreads();
        }

        // prefetch xproj gates for pointwise tail (DRAM latency overlap)
        float2 xg[4];
        {
            size_t xb = ((size_t)pm * Tq + t) * G4 + pcol;
#pragma unroll
            for (int gg = 0; gg < 4; gg++)
                xg[gg] = *(const float2*)&xproj[xb + (size_t)gg * Hq];
        }

        float acc[2][4] = {};

        // stage chunk 0 (L2-coherent loads, tf32 round)
        float4 pre[8];
#pragma unroll
        for (int p = 0; p < 8; p++)
            pre[p] = __ldcg((const float4*)&h_in[(p * 8 + ldrow) * Hq + ldc4]);
#pragma unroll
        for (int p = 0; p < 8; p++) {
            float4 r; r.x = tf32r(pre[p].x); r.y = tf32r(pre[p].y);
                      r.z = tf32r(pre[p].z); r.w = tf32r(pre[p].w);
            *(float4*)&HsA[(p * 8 + ldrow) * HST + ldc4] = r;
        }
        __syncthreads();

        for (int kt = 0; kt < 8; kt++) {
            if (kt < 7) {
                const int k0 = (kt + 1) * 128;
#pragma unroll
                for (int p = 0; p < 8; p++)
                    pre[p] = __ldcg((const float4*)&h_in[(p * 8 + ldrow) * Hq + k0 + ldc4]);
            }
            const float* Hs = HsA + (kt & 1) * CHUNK_F;
#pragma unroll
            for (int ks = 0; ks < 16; ks++) {
                const int kb = ks * 8;
                float4 wv = Wb4[(((kt * 16 + ks) * 2) + wn) * 32 + lane];
                uint32_t a0 = fu(Hs[r0 * HST + kb + tq]);
                uint32_t a1 = fu(Hs[(r0 + 8) * HST + kb + tq]);
                uint32_t a2 = fu(Hs[r0 * HST + kb + tq + 4]);
                uint32_t a3 = fu(Hs[(r0 + 8) * HST + kb + tq + 4]);
                mma_tf32(acc[0], a0, a1, a2, a3, fu(wv.x), fu(wv.y));
                mma_tf32(acc[1], a0, a1, a2, a3, fu(wv.z), fu(wv.w));
            }
            if (kt < 7) {
                float* HsN = HsA + ((kt + 1) & 1) * CHUNK_F;
#pragma unroll
                for (int p = 0; p < 8; p++) {
                    float4 r; r.x = tf32r(pre[p].x); r.y = tf32r(pre[p].y);
                              r.z = tf32r(pre[p].z); r.w = tf32r(pre[p].w);
                    *(float4*)&HsN[(p * 8 + ldrow) * HST + ldc4] = r;
                }
            }
            __syncthreads();
        }

        // stage gate tile: Cs[m][0..31] with stride 33 (aliases h buffer 0)
        float* Cs = HsA;
        {
            int cb = wn * 16;
#pragma unroll
            for (int nt = 0; nt < 2; nt++) {
                int col = cb + nt * 8 + 2 * tq;
                Cs[r0 * 33 + col]           = acc[nt][0];
                Cs[r0 * 33 + col + 1]       = acc[nt][1];
                Cs[(r0 + 8) * 33 + col]     = acc[nt][2];
                Cs[(r0 + 8) * 33 + col + 1] = acc[nt][3];
            }
        }
        __syncthreads();

        // pointwise: each thread does 2 columns, c kept in registers
        {
            const float* cr = &Cs[pm * 33 + pj];
            float hn0, hn1;
            {
                float ig = cr[0]  + xg[0].x;
                float fg = cr[8]  + xg[1].x;
                float gg = cr[16] + xg[2].x;
                float og = cr[24] + xg[3].x;
                float cn = sigm(fg) * creg.x + sigm(ig) * tanhf(gg);
                creg.x = cn; hn0 = sigm(og) * tanhf(cn);
            }
            {
                float ig = cr[1]  + xg[0].y;
                float fg = cr[9]  + xg[1].y;
                float gg = cr[17] + xg[2].y;
                float og = cr[25] + xg[3].y;
                float cn = sigm(fg) * creg.y + sigm(ig) * tanhf(gg);
                creg.y = cn; hn1 = sigm(og) * tanhf(cn);
            }
            float2 hv = {hn0, hn1};
            *(float2*)&h_out[pm * Hq + pcol] = hv;
            if (!enc) *(float2*)&dec_hs[((size_t)pm * Tq + t) * Hq + pcol] = hv;
        }

        grid_bar((unsigned)(s + 1) * NCTA);
    }
}

// ---------------- host driver ------------------------------------------------
extern "C" void kernel_launch(void* const* d_in, const int* in_sizes, int n_in,
                              void* d_out, int out_size)
{
    const float* input_seq  = (const float*)d_in[0];
    const float* target_seq = (const float*)d_in[1];
    const float* enc_Wih = (const float*)d_in[2];
    const float* enc_Whh = (const float*)d_in[3];
    const float* enc_bih = (const float*)d_in[4];
    const float* enc_bhh = (const float*)d_in[5];
    const float* dec_Wih = (const float*)d_in[6];
    const float* dec_Whh = (const float*)d_in[7];
    const float* dec_bih = (const float*)d_in[8];
    const float* dec_bhh = (const float*)d_in[9];
    const float* W1 = (const float*)d_in[10];
    const float* b1 = (const float*)d_in[11];
    const float* W2 = (const float*)d_in[12];
    const float* b2 = (const float*)d_in[13];
    const float* W3 = (const float*)d_in[14];
    const float* b3 = (const float*)d_in[15];
    float* out = (float*)d_out;

    float *enc_xp, *dec_xp, *dec_hs, *m1, *m2, *wte, *wtd;
    cudaGetSymbolAddress((void**)&enc_xp, g_enc_xproj);
    cudaGetSymbolAddress((void**)&dec_xp, g_dec_xproj);
    cudaGetSymbolAddress((void**)&dec_hs, g_dec_hs);
    cudaGetSymbolAddress((void**)&m1,     g_mlp1);
    cudaGetSymbolAddress((void**)&m2,     g_mlp2);
    cudaGetSymbolAddress((void**)&wte,    g_Wt_enc);
    cudaGetSymbolAddress((void**)&wtd,    g_Wt_dec);

    static int smem_set = 0;
    if (!smem_set) {
        cudaFuncSetAttribute(lstm_persistent_kernel,
                             cudaFuncAttributeMaxDynamicSharedMemorySize, LSTM_SMEM);
        smem_set = 1;
    }

    zero_hc_kernel<<<(Bq * Hq + 255) / 256, 256>>>();

    prep_w_kernel<<<4096, 256>>>(enc_Whh, (float4*)wte);
    prep_w_kernel<<<4096, 256>>>(dec_Whh, (float4*)wtd);

    // time-parallel input projections (biases folded)
    gemm_tf32_kernel<<<dim3(G4 / 128, MTOT / 128), 256>>>(
        input_seq, enc_Wih, enc_bih, enc_bhh, enc_xp, MTOT, G4, 256, 0);
    gemm_tf32_kernel<<<dim3(G4 / 128, MTOT / 128), 256>>>(
        target_seq, dec_Wih, dec_bih, dec_bhh, dec_xp, MTOT, G4, Hq, 0);

    // recurrence: one persistent launch, 1024 steps
    lstm_persistent_kernel<<<NCTA, 256, LSTM_SMEM>>>(enc_xp, dec_xp, dec_hs);

    // MLP head
    gemm_tf32_kernel<<<dim3(256 / 128, MTOT / 128), 256>>>(
        dec_hs, W1, b1, nullptr, m1, MTOT, 256, Hq, 1);
    gemm_tf32_kernel<<<dim3(128 / 128, MTOT / 128), 256>>>(
        m1, W2, b2, nullptr, m2, MTOT, 128, 256, 1);
    gemm_tf32_kernel<<<dim3(256 / 128, MTOT / 128), 256>>>(
        m2, W3, b3, nullptr, out, MTOT, 256, 128, 0);
}